// round 7
// baseline (speedup 1.0000x reference)
#include <cuda_runtime.h>
#include <math.h>

#define Bq 4
#define Lq 4096
#define Hq 8
#define Dq 64
#define SK 9
#define U  9
#define BH (Bq*Hq)
#define NCH 8
#define CHK (Lq/NCH)   // 512

// scratch (static __device__ arrays — no allocation)
__device__ float  g_M[BH * Lq];
__device__ int    g_top[BH * U];
__device__ float4 g_vmean4[BH * (Dq/4)];
__device__ float  g_vpart[BH * NCH * Dq];
__device__ float  g_cand_v[BH * NCH * U];
__device__ int    g_cand_i[BH * NCH * U];
__device__ int    g_cnt[BH];
__device__ float  g_scores[BH * U * Lq];        // raw scores, then normalized attn

// ---------------------------------------------------------------------------
// L0: zero the merge counters (tiny)
// ---------------------------------------------------------------------------
__global__ void __launch_bounds__(32)
k_zero()
{
    if (threadIdx.x < BH) g_cnt[threadIdx.x] = 0;
}

// ---------------------------------------------------------------------------
// L1/L2: V mean partials, split in two launches (chunk halves)
// grid = BH*4, 256 threads
// ---------------------------------------------------------------------------
__global__ void __launch_bounds__(256)
k_vmean_part(const float* __restrict__ v, int ch0)
{
    int bh = blockIdx.x >> 2, ch = (blockIdx.x & 3) + ch0;
    int b = bh / Hq, h = bh % Hq;
    int t = threadIdx.x;
    int d = t & 63, g = t >> 6;          // 4 l-groups x 64 d
    float acc = 0.f;
    int lend = (ch + 1) * CHK;
    for (int l = ch * CHK + g; l < lend; l += 4)
        acc += v[((size_t)(b * Lq + l) * Hq + h) * Dq + d];
    __shared__ float red[256];
    red[t] = acc;
    __syncthreads();
    if (t < 128) red[t] += red[t + 128];
    __syncthreads();
    if (t < 64) g_vpart[(bh * NCH + ch) * Dq + t] = red[t] + red[t + 64];
}

// ---------------------------------------------------------------------------
// L3: sampled scores. One warp per (b,l) covering ALL 8 heads.
// Per sample: one contiguous 2KB K-row load; per-float4 dots reduce so reg r
// half h holds head 2r+half. grid = Bq*Lq/4 blocks of 128.
// ---------------------------------------------------------------------------
__global__ void __launch_bounds__(128)
k_sample(const float* __restrict__ q,
         const float* __restrict__ k,
         const int*   __restrict__ idx)
{
    int warp = (blockIdx.x * 128 + threadIdx.x) >> 5;   // 0..Bq*Lq-1
    int lane = threadIdx.x & 31;
    int l = warp & (Lq - 1);
    int b = warp >> 12;

    const float4* qrow = (const float4*)(q + (size_t)(b * Lq + l) * Hq * Dq);
    float4 q4[4];
#pragma unroll
    for (int r = 0; r < 4; r++) q4[r] = qrow[lane + 32 * r];

    int ks[SK];
#pragma unroll
    for (int s = 0; s < SK; s++) ks[s] = idx[l * SK + s];

    int half = lane >> 4;
    int rsel = lane & 15;        // lanes with rsel<4 track head 2*rsel+half

    float mx = -INFINITY, sm = 0.f;
#pragma unroll
    for (int g3 = 0; g3 < SK; g3 += 3) {
        float4 kv[3][4];
#pragma unroll
        for (int j = 0; j < 3; j++) {
            const float4* krow = (const float4*)(k + (size_t)(b * Lq + ks[g3 + j]) * Hq * Dq);
#pragma unroll
            for (int r = 0; r < 4; r++) kv[j][r] = krow[lane + 32 * r];
        }
#pragma unroll
        for (int j = 0; j < 3; j++) {
#pragma unroll
            for (int r = 0; r < 4; r++) {
                float p = kv[j][r].x * q4[r].x + kv[j][r].y * q4[r].y
                        + kv[j][r].z * q4[r].z + kv[j][r].w * q4[r].w;
                p += __shfl_xor_sync(0xffffffffu, p, 1);
                p += __shfl_xor_sync(0xffffffffu, p, 2);
                p += __shfl_xor_sync(0xffffffffu, p, 4);
                p += __shfl_xor_sync(0xffffffffu, p, 8);
                if (rsel == r) { mx = fmaxf(mx, p); sm += p; }
            }
        }
    }

    if (rsel < 4) {
        int h = 2 * rsel + half;
        g_M[(b * Hq + h) * Lq + l] = mx - sm * (1.0f / (float)Lq);
    }
}

// ---------------------------------------------------------------------------
// L4: per-chunk top-9; last finishing block per bh merges candidates + vmean
// grid = bh*NCH, 128 threads
// ---------------------------------------------------------------------------
__global__ void __launch_bounds__(128)
k_topk()
{
    int blk = blockIdx.x;
    int bh = blk >> 3, ch = blk & 7;
    int base = ch * CHK;
    int t = threadIdx.x;

    __shared__ float sv[CHK];
    __shared__ float rv[128];
    __shared__ int   ri[128];

    for (int i = t; i < CHK; i += 128) sv[i] = g_M[bh * Lq + base + i];
    __syncthreads();

    for (int r = 0; r < U; r++) {
        float bv = -INFINITY; int bi = 0x7fffffff;
#pragma unroll
        for (int j = 0; j < CHK / 128; j++) {
            int i = t + j * 128;
            float vv = sv[i];
            if (vv > bv || (vv == bv && i < bi)) { bv = vv; bi = i; }
        }
        rv[t] = bv; ri[t] = bi;
        __syncthreads();
        for (int o = 64; o > 0; o >>= 1) {
            if (t < o) {
                float v2 = rv[t + o]; int i2 = ri[t + o];
                if (v2 > rv[t] || (v2 == rv[t] && i2 < ri[t])) { rv[t] = v2; ri[t] = i2; }
            }
            __syncthreads();
        }
        if (t == 0) {
            g_cand_v[blk * U + r] = rv[0];
            g_cand_i[blk * U + r] = base + ri[0];
            sv[ri[0]] = -INFINITY;
        }
        __syncthreads();
    }

    __threadfence();
    __shared__ int is_last;
    if (t == 0) is_last = (atomicAdd(&g_cnt[bh], 1) == NCH - 1);
    __syncthreads();
    if (!is_last) return;

    if (t >= 32 && t < 96) {
        int d = t - 32;
        float s = 0.f;
#pragma unroll
        for (int c = 0; c < NCH; c++) s += g_vpart[(bh * NCH + c) * Dq + d];
        ((float*)g_vmean4)[bh * Dq + d] = s * (1.0f / (float)Lq);
    }

    if (t < 32) {
        const int NC = NCH * U;          // 72
        float v0 = -INFINITY, v1 = -INFINITY, v2 = -INFINITY;
        int   i0 = 0x7fffffff, i1 = 0x7fffffff, i2 = 0x7fffffff;
        if (t      < NC) { v0 = g_cand_v[bh * NC + t];      i0 = g_cand_i[bh * NC + t]; }
        if (t + 32 < NC) { v1 = g_cand_v[bh * NC + t + 32]; i1 = g_cand_i[bh * NC + t + 32]; }
        if (t + 64 < NC) { v2 = g_cand_v[bh * NC + t + 64]; i2 = g_cand_i[bh * NC + t + 64]; }

        for (int r = 0; r < U; r++) {
            float bv = v0; int bi = i0;
            if (v1 > bv || (v1 == bv && i1 < bi)) { bv = v1; bi = i1; }
            if (v2 > bv || (v2 == bv && i2 < bi)) { bv = v2; bi = i2; }
#pragma unroll
            for (int o = 16; o > 0; o >>= 1) {
                float ov = __shfl_xor_sync(0xffffffffu, bv, o);
                int   oi = __shfl_xor_sync(0xffffffffu, bi, o);
                if (ov > bv || (ov == bv && oi < bi)) { bv = ov; bi = oi; }
            }
            if (t == 0) g_top[bh * U + r] = bi;
            if (i0 == bi) v0 = -INFINITY;
            if (i1 == bi) v1 = -INFINITY;
            if (i2 == bi) v2 = -INFINITY;
        }
    }
}

// ---------------------------------------------------------------------------
// L5: broadcast V-mean into context; top-u rows get 0 (ctx atomicAdds later)
// ---------------------------------------------------------------------------
#define NBCAST ((Bq*Lq*Hq*Dq/4)/256)   // 8192

__global__ void __launch_bounds__(256)
k_bcast(float4* __restrict__ out4)
{
    int f = blockIdx.x * 256 + threadIdx.x;
    int b = f >> 19;
    int h = (f >> 4) & 7;
    int l = (f >> 7) & 4095;
    int bh = b * Hq + h;
    bool hit = false;
#pragma unroll
    for (int r = 0; r < U; r++) hit |= (g_top[bh * U + r] == l);
    float4 z = make_float4(0.f, 0.f, 0.f, 0.f);
    out4[f] = hit ? z : g_vmean4[(bh << 4) + (f & 15)];
}

// ---------------------------------------------------------------------------
// L6: raw scores for top-u queries; grid = bh*NCH, 256 threads
// ---------------------------------------------------------------------------
__global__ void __launch_bounds__(256)
k_scores(const float* __restrict__ q, const float* __restrict__ k)
{
    int blk = blockIdx.x;
    int bh = blk >> 3, ch = blk & 7;
    int b = bh / Hq, h = bh % Hq;
    int t = threadIdx.x;

    __shared__ float qr[U * Dq];
    for (int i = t; i < U * Dq; i += 256) {
        int r = i >> 6, d = i & 63;
        int l = g_top[bh * U + r];
        qr[i] = q[((size_t)(b * Lq + l) * Hq + h) * Dq + d];
    }
    __syncthreads();

    const float scale = 0.125f;
    int kend = (ch + 1) * CHK;
    for (int kk = ch * CHK + t; kk < kend; kk += 256) {
        const float4* krow = (const float4*)(k + ((size_t)(b * Lq + kk) * Hq + h) * Dq);
        float dot[U];
#pragma unroll
        for (int r = 0; r < U; r++) dot[r] = 0.f;
#pragma unroll
        for (int i = 0; i < Dq / 4; i++) {
            float4 kv = krow[i];
#pragma unroll
            for (int r = 0; r < U; r++) {
                dot[r] += kv.x * qr[r * Dq + 4 * i + 0]
                        + kv.y * qr[r * Dq + 4 * i + 1]
                        + kv.z * qr[r * Dq + 4 * i + 2]
                        + kv.w * qr[r * Dq + 4 * i + 3];
            }
        }
#pragma unroll
        for (int r = 0; r < U; r++) g_scores[((size_t)(bh * U + r)) * Lq + kk] = dot[r] * scale;
    }
}

// ---------------------------------------------------------------------------
// L7: softmax per row + attn output write; grid = bh*U, 512 threads
// ---------------------------------------------------------------------------
__global__ void __launch_bounds__(512)
k_softmax(float* __restrict__ out)
{
    int blk = blockIdx.x;                 // = bh*U + r, matches attn layout (b,h,u,l)
    float* row = g_scores + (size_t)blk * Lq;
    __shared__ float sr[Lq];
    __shared__ float red[512];
    int t = threadIdx.x;

    float mx = -INFINITY;
    for (int kk = t; kk < Lq; kk += 512) {
        float s = row[kk];
        sr[kk] = s;
        mx = fmaxf(mx, s);
    }
    red[t] = mx; __syncthreads();
    for (int o = 256; o > 0; o >>= 1) {
        if (t < o) red[t] = fmaxf(red[t], red[t + o]);
        __syncthreads();
    }
    mx = red[0]; __syncthreads();

    float sm = 0.f;
    for (int kk = t; kk < Lq; kk += 512) {
        float e = expf(sr[kk] - mx);
        sr[kk] = e;
        sm += e;
    }
    red[t] = sm; __syncthreads();
    for (int o = 256; o > 0; o >>= 1) {
        if (t < o) red[t] += red[t + o];
        __syncthreads();
    }
    float inv = 1.0f / red[0];

    float* attn = out + (size_t)Bq * Lq * Hq * Dq + (size_t)blk * Lq;
    for (int kk = t; kk < Lq; kk += 512) {
        float a = sr[kk] * inv;
        row[kk] = a;
        attn[kk] = a;
    }
}

// ---------------------------------------------------------------------------
// L8: ctx partials, atomically accumulated into the (pre-zeroed) top rows
// grid = bh*NCH, 512 threads
// ---------------------------------------------------------------------------
__global__ void __launch_bounds__(512)
k_ctx(const float* __restrict__ v, float* __restrict__ out)
{
    int blk = blockIdx.x;
    int bh = blk >> 3, ch = blk & 7;
    int b = bh / Hq, h = bh % Hq;
    int t = threadIdx.x;
    int d = t & 63, g = t >> 6;           // 8 k-groups x 64 d

    const float* sc = g_scores + (size_t)bh * U * Lq;
    float acc[U];
#pragma unroll
    for (int r = 0; r < U; r++) acc[r] = 0.f;

    int kend = (ch + 1) * CHK;
    for (int kk = ch * CHK + g; kk < kend; kk += 8) {
        float vv = v[((size_t)(b * Lq + kk) * Hq + h) * Dq + d];
#pragma unroll
        for (int r = 0; r < U; r++) acc[r] += sc[r * Lq + kk] * vv;
    }

    __shared__ float cred[8 * U * Dq];
#pragma unroll
    for (int r = 0; r < U; r++) cred[((g * U + r) << 6) + d] = acc[r];
    __syncthreads();

    for (int i = t; i < U * Dq; i += 512) {
        int r = i >> 6, dd = i & 63;
        float s = 0.f;
#pragma unroll
        for (int gg = 0; gg < 8; gg++) s += cred[((gg * U + r) << 6) + dd];
        int l = g_top[bh * U + r];
        atomicAdd(&out[((size_t)(b * Lq + l) * Hq + h) * Dq + dd], s);
    }
}

// ---------------------------------------------------------------------------
extern "C" void kernel_launch(void* const* d_in, const int* in_sizes, int n_in,
                              void* d_out, int out_size)
{
    const float* q   = (const float*)d_in[0];
    const float* k   = (const float*)d_in[1];
    const float* v   = (const float*)d_in[2];
    const int*   idx = (const int*)d_in[3];
    float* out = (float*)d_out;

    (void)in_sizes; (void)n_in; (void)out_size;

    k_zero<<<1, 32>>>();                              // 0
    k_vmean_part<<<BH * 4, 256>>>(v, 0);              // 1
    k_vmean_part<<<BH * 4, 256>>>(v, 4);              // 2
    k_sample<<<(Bq * Lq) / 4, 128>>>(q, k, idx);      // 3  <- profiled slot
    k_topk<<<BH * NCH, 128>>>();                      // 4
    k_bcast<<<NBCAST, 256>>>((float4*)out);           // 5
    k_scores<<<BH * NCH, 256>>>(q, k);                // 6
    k_softmax<<<BH * U, 512>>>(out);                  // 7
    k_ctx<<<BH * NCH, 512>>>(v, out);                 // 8
}

// round 8
// speedup vs baseline: 2.4011x; 2.4011x over previous
#include <cuda_runtime.h>
#include <math.h>

#define Bq 4
#define Lq 4096
#define Hq 8
#define Dq 64
#define SK 9
#define U  9
#define BH (Bq*Hq)
#define NCH 8
#define CHK (Lq/NCH)   // 512

// scratch (static __device__ arrays — no allocation)
__device__ float  g_M[BH * Lq];
__device__ int    g_top[BH * U];
__device__ float4 g_vmean4[BH * (Dq/4)];
__device__ float  g_cand_v[BH * NCH * U];
__device__ int    g_cand_i[BH * NCH * U];
__device__ int    g_cnt[BH];
__device__ int    g_cnt2[BH];
__device__ float  g_scores[BH * U * Lq];          // raw (scaled) scores
__device__ float  g_cmax[BH * NCH * U];           // per-chunk row max
__device__ float  g_csum[BH * NCH * U];           // per-chunk row sum(exp(s-m_c))
__device__ float  g_part[BH * NCH * 10 * Dq];     // per-chunk: 9 ctx rows + vsum
__device__ float  g_ctxtop[BH * U * Dq];

// ---------------------------------------------------------------------------
// L0: zero the merge counters (tiny)
// ---------------------------------------------------------------------------
__global__ void __launch_bounds__(64)
k_zero()
{
    if (threadIdx.x < BH) { g_cnt[threadIdx.x] = 0; g_cnt2[threadIdx.x] = 0; }
}

// ---------------------------------------------------------------------------
// L1: sampled scores. One warp per (b,l) covering ALL 8 heads.
// ---------------------------------------------------------------------------
__global__ void __launch_bounds__(128)
k_sample(const float* __restrict__ q,
         const float* __restrict__ k,
         const int*   __restrict__ idx)
{
    int warp = (blockIdx.x * 128 + threadIdx.x) >> 5;   // 0..Bq*Lq-1
    int lane = threadIdx.x & 31;
    int l = warp & (Lq - 1);
    int b = warp >> 12;

    const float4* qrow = (const float4*)(q + (size_t)(b * Lq + l) * Hq * Dq);
    float4 q4[4];
#pragma unroll
    for (int r = 0; r < 4; r++) q4[r] = qrow[lane + 32 * r];

    int ks[SK];
#pragma unroll
    for (int s = 0; s < SK; s++) ks[s] = idx[l * SK + s];

    int half = lane >> 4;
    int rsel = lane & 15;        // lanes with rsel<4 track head 2*rsel+half

    float mx = -INFINITY, sm = 0.f;
#pragma unroll
    for (int g3 = 0; g3 < SK; g3 += 3) {
        float4 kv[3][4];
#pragma unroll
        for (int j = 0; j < 3; j++) {
            const float4* krow = (const float4*)(k + (size_t)(b * Lq + ks[g3 + j]) * Hq * Dq);
#pragma unroll
            for (int r = 0; r < 4; r++) kv[j][r] = krow[lane + 32 * r];
        }
#pragma unroll
        for (int j = 0; j < 3; j++) {
#pragma unroll
            for (int r = 0; r < 4; r++) {
                float p = kv[j][r].x * q4[r].x + kv[j][r].y * q4[r].y
                        + kv[j][r].z * q4[r].z + kv[j][r].w * q4[r].w;
                p += __shfl_xor_sync(0xffffffffu, p, 1);
                p += __shfl_xor_sync(0xffffffffu, p, 2);
                p += __shfl_xor_sync(0xffffffffu, p, 4);
                p += __shfl_xor_sync(0xffffffffu, p, 8);
                if (rsel == r) { mx = fmaxf(mx, p); sm += p; }
            }
        }
    }

    if (rsel < 4) {
        int h = 2 * rsel + half;
        g_M[(b * Hq + h) * Lq + l] = mx - sm * (1.0f / (float)Lq);
    }
}

// ---------------------------------------------------------------------------
// L2: per-chunk top-9; last finishing block per bh merges candidates
// grid = bh*NCH, 128 threads
// ---------------------------------------------------------------------------
__global__ void __launch_bounds__(128)
k_topk()
{
    int blk = blockIdx.x;
    int bh = blk >> 3, ch = blk & 7;
    int base = ch * CHK;
    int t = threadIdx.x;

    __shared__ float sv[CHK];
    __shared__ float rv[128];
    __shared__ int   ri[128];

    for (int i = t; i < CHK; i += 128) sv[i] = g_M[bh * Lq + base + i];
    __syncthreads();

    for (int r = 0; r < U; r++) {
        float bv = -INFINITY; int bi = 0x7fffffff;
#pragma unroll
        for (int j = 0; j < CHK / 128; j++) {
            int i = t + j * 128;
            float vv = sv[i];
            if (vv > bv || (vv == bv && i < bi)) { bv = vv; bi = i; }
        }
        rv[t] = bv; ri[t] = bi;
        __syncthreads();
        for (int o = 64; o > 0; o >>= 1) {
            if (t < o) {
                float v2 = rv[t + o]; int i2 = ri[t + o];
                if (v2 > rv[t] || (v2 == rv[t] && i2 < ri[t])) { rv[t] = v2; ri[t] = i2; }
            }
            __syncthreads();
        }
        if (t == 0) {
            g_cand_v[blk * U + r] = rv[0];
            g_cand_i[blk * U + r] = base + ri[0];
            sv[ri[0]] = -INFINITY;
        }
        __syncthreads();
    }

    __threadfence();
    __shared__ int is_last;
    if (t == 0) is_last = (atomicAdd(&g_cnt[bh], 1) == NCH - 1);
    __syncthreads();
    if (!is_last || t >= 32) return;

    const int NC = NCH * U;          // 72
    float v0 = -INFINITY, v1 = -INFINITY, v2 = -INFINITY;
    int   i0 = 0x7fffffff, i1 = 0x7fffffff, i2 = 0x7fffffff;
    if (t      < NC) { v0 = g_cand_v[bh * NC + t];      i0 = g_cand_i[bh * NC + t]; }
    if (t + 32 < NC) { v1 = g_cand_v[bh * NC + t + 32]; i1 = g_cand_i[bh * NC + t + 32]; }
    if (t + 64 < NC) { v2 = g_cand_v[bh * NC + t + 64]; i2 = g_cand_i[bh * NC + t + 64]; }

    for (int r = 0; r < U; r++) {
        float bv = v0; int bi = i0;
        if (v1 > bv || (v1 == bv && i1 < bi)) { bv = v1; bi = i1; }
        if (v2 > bv || (v2 == bv && i2 < bi)) { bv = v2; bi = i2; }
#pragma unroll
        for (int o = 16; o > 0; o >>= 1) {
            float ov = __shfl_xor_sync(0xffffffffu, bv, o);
            int   oi = __shfl_xor_sync(0xffffffffu, bi, o);
            if (ov > bv || (ov == bv && oi < bi)) { bv = ov; bi = oi; }
        }
        if (t == 0) g_top[bh * U + r] = bi;
        if (i0 == bi) v0 = -INFINITY;
        if (i1 == bi) v1 = -INFINITY;
        if (i2 == bi) v2 = -INFINITY;
    }
}

// ---------------------------------------------------------------------------
// L3 (profiled): raw scores + per-chunk softmax stats; grid = bh*NCH, 256 thr
// ---------------------------------------------------------------------------
__global__ void __launch_bounds__(256)
k_scores(const float* __restrict__ q, const float* __restrict__ k)
{
    int blk = blockIdx.x;
    int bh = blk >> 3, ch = blk & 7;
    int b = bh / Hq, h = bh % Hq;
    int t = threadIdx.x;
    int wid = t >> 5, lane = t & 31;

    __shared__ float qr[U * Dq];
    __shared__ float red8[8];
    for (int i = t; i < U * Dq; i += 256) {
        int r = i >> 6, d = i & 63;
        int l = g_top[bh * U + r];
        qr[i] = q[((size_t)(b * Lq + l) * Hq + h) * Dq + d];
    }
    __syncthreads();

    const float scale = 0.125f;
    int base = ch * CHK;
    float s0[U], s1[U];
#pragma unroll
    for (int it = 0; it < 2; it++) {
        int kk = base + t + it * 256;
        const float4* krow = (const float4*)(k + ((size_t)(b * Lq + kk) * Hq + h) * Dq);
        float dot[U];
#pragma unroll
        for (int r = 0; r < U; r++) dot[r] = 0.f;
#pragma unroll
        for (int i = 0; i < Dq / 4; i++) {
            float4 kv = krow[i];
#pragma unroll
            for (int r = 0; r < U; r++) {
                dot[r] += kv.x * qr[r * Dq + 4 * i + 0]
                        + kv.y * qr[r * Dq + 4 * i + 1]
                        + kv.z * qr[r * Dq + 4 * i + 2]
                        + kv.w * qr[r * Dq + 4 * i + 3];
            }
        }
#pragma unroll
        for (int r = 0; r < U; r++) {
            float s = dot[r] * scale;
            g_scores[((size_t)(bh * U + r)) * Lq + kk] = s;
            if (it == 0) s0[r] = s; else s1[r] = s;
        }
    }

    // per-row chunk max + sum(exp(s - m_c))
    for (int r = 0; r < U; r++) {
        float m = fmaxf(s0[r], s1[r]);
#pragma unroll
        for (int o = 16; o > 0; o >>= 1) m = fmaxf(m, __shfl_xor_sync(0xffffffffu, m, o));
        if (lane == 0) red8[wid] = m;
        __syncthreads();
        float m_c = red8[0];
#pragma unroll
        for (int j = 1; j < 8; j++) m_c = fmaxf(m_c, red8[j]);
        __syncthreads();

        float e = expf(s0[r] - m_c) + expf(s1[r] - m_c);
#pragma unroll
        for (int o = 16; o > 0; o >>= 1) e += __shfl_xor_sync(0xffffffffu, e, o);
        if (lane == 0) red8[wid] = e;
        __syncthreads();
        float S_c = 0.f;
#pragma unroll
        for (int j = 0; j < 8; j++) S_c += red8[j];
        __syncthreads();

        if (t == 0) { g_cmax[blk * U + r] = m_c; g_csum[blk * U + r] = S_c; }
    }
}

// ---------------------------------------------------------------------------
// L4: attn write + ctx partials + V sum, per (bh, chunk); 512 threads
// ---------------------------------------------------------------------------
__global__ void __launch_bounds__(512, 1)
k_attn_ctx(const float* __restrict__ v, float* __restrict__ out)
{
    int blk = blockIdx.x;
    int bh = blk >> 3, ch = blk & 7;
    int b = bh / Hq, h = bh % Hq;
    int t = threadIdx.x;

    __shared__ float sa[U * CHK];          // normalized attn for this chunk
    __shared__ float sm_m[U], sm_is[U];
    __shared__ float cred[8 * 10 * Dq];

    if (t < U) {
        float m_r = -INFINITY;
#pragma unroll
        for (int c = 0; c < NCH; c++) m_r = fmaxf(m_r, g_cmax[(bh * NCH + c) * U + t]);
        float S = 0.f;
#pragma unroll
        for (int c = 0; c < NCH; c++)
            S += g_csum[(bh * NCH + c) * U + t] * expf(g_cmax[(bh * NCH + c) * U + t] - m_r);
        sm_m[t] = m_r;
        sm_is[t] = 1.0f / S;
    }
    __syncthreads();

    // pass 1: coalesced attn computation + write
    float* attn = out + (size_t)Bq * Lq * Hq * Dq + (size_t)bh * U * Lq;
    int base = ch * CHK;
    for (int i = t; i < U * CHK; i += 512) {
        int r = i >> 9, j = i & (CHK - 1);
        float s = g_scores[((size_t)(bh * U + r)) * Lq + base + j];
        float a = expf(s - sm_m[r]) * sm_is[r];
        sa[i] = a;
        attn[(size_t)r * Lq + base + j] = a;
    }
    __syncthreads();

    // pass 2: ctx partials + V sum (single V read)
    {
        int d = t & 63, g = t >> 6;       // 8 k-groups x 64 d
        float acc[U];
        float accv = 0.f;
#pragma unroll
        for (int r = 0; r < U; r++) acc[r] = 0.f;
        for (int j = g; j < CHK; j += 8) {
            float vv = v[((size_t)(b * Lq + base + j) * Hq + h) * Dq + d];
            accv += vv;
#pragma unroll
            for (int r = 0; r < U; r++) acc[r] += sa[(r << 9) + j] * vv;
        }
#pragma unroll
        for (int r = 0; r < U; r++) cred[((g * 10 + r) << 6) + d] = acc[r];
        cred[((g * 10 + 9) << 6) + d] = accv;
    }
    __syncthreads();

    for (int i = t; i < 10 * Dq; i += 512) {
        int row = i >> 6, dd = i & 63;
        float s = 0.f;
#pragma unroll
        for (int gg = 0; gg < 8; gg++) s += cred[((gg * 10 + row) << 6) + dd];
        g_part[((size_t)(bh * NCH + ch) * 10 + row) * Dq + dd] = s;
    }

    // last block of this bh: final reduce -> ctx_top + vmean
    __threadfence();
    __shared__ int is_last;
    if (t == 0) is_last = (atomicAdd(&g_cnt2[bh], 1) == NCH - 1);
    __syncthreads();
    if (!is_last) return;

    for (int i = t; i < 10 * Dq; i += 512) {
        int row = i >> 6, dd = i & 63;
        float s = 0.f;
#pragma unroll
        for (int c = 0; c < NCH; c++)
            s += g_part[((size_t)(bh * NCH + c) * 10 + row) * Dq + dd];
        if (row < U) g_ctxtop[(bh * U + row) * Dq + dd] = s;
        else ((float*)g_vmean4)[bh * Dq + dd] = s * (1.0f / (float)Lq);
    }
}

// ---------------------------------------------------------------------------
// L5: final context write: vmean everywhere, ctx_top at top rows
// ---------------------------------------------------------------------------
#define NBCAST ((Bq*Lq*Hq*Dq/4)/256)   // 8192

__global__ void __launch_bounds__(256)
k_bcast(float4* __restrict__ out4)
{
    int f = blockIdx.x * 256 + threadIdx.x;
    int b = f >> 19;
    int h = (f >> 4) & 7;
    int l = (f >> 7) & 4095;
    int bh = b * Hq + h;
    int rr = -1;
#pragma unroll
    for (int r = 0; r < U; r++) if (g_top[bh * U + r] == l) rr = r;
    float4 val;
    if (rr >= 0) val = ((const float4*)g_ctxtop)[(bh * U + rr) * 16 + (f & 15)];
    else         val = g_vmean4[(bh << 4) + (f & 15)];
    out4[f] = val;
}

// ---------------------------------------------------------------------------
extern "C" void kernel_launch(void* const* d_in, const int* in_sizes, int n_in,
                              void* d_out, int out_size)
{
    const float* q   = (const float*)d_in[0];
    const float* k   = (const float*)d_in[1];
    const float* v   = (const float*)d_in[2];
    const int*   idx = (const int*)d_in[3];
    float* out = (float*)d_out;

    (void)in_sizes; (void)n_in; (void)out_size;

    k_zero<<<1, 64>>>();                              // 0
    k_sample<<<(Bq * Lq) / 4, 128>>>(q, k, idx);      // 1
    k_topk<<<BH * NCH, 128>>>();                      // 2
    k_scores<<<BH * NCH, 256>>>(q, k);                // 3  <- profiled slot
    k_attn_ctx<<<BH * NCH, 512>>>(v, out);            // 4
    k_bcast<<<NBCAST, 256>>>((float4*)out);           // 5
}